// round 14
// baseline (speedup 1.0000x reference)
#include <cuda_runtime.h>
#include <cuda_bf16.h>
#include <cstdint>
#include <math.h>

// ---------------------------------------------------------------------------
// Fixed problem dimensions
// ---------------------------------------------------------------------------
#define DD     128
#define NLIT   32000
#define NCL    64000
#define NEDGE  192000
#define NB     32
#define GPL    1000
#define NITER  4
#define NG     512

#define KBC    8            // clause k-blocks of 32  (KTOT=256)
#define KBL    12           // literal k-blocks of 32 (KTOT=384)

// SMEM tile geometry: pitch 40 halves (80B) per 32-k row, conflict-free
#define PITCHB   80
#define OFF_ALO  10240
#define OFF_BHI  20480
#define OFF_BLO  30720
#define BUF_BYTES 40960
#define SMEMB    (2 * BUF_BYTES)

// ---------------------------------------------------------------------------
// Device-global state (no allocations allowed)
// ---------------------------------------------------------------------------
__device__ float g_hl[2][NLIT * DD];
__device__ float g_cl[NLIT * DD];
__device__ float g_hc[2][NCL * DD];
__device__ float g_cc[NCL * DD];
// Pre-converted A operands (bf16 hi/lo)
__device__ __align__(16) unsigned short g_Ac_hi[NCL * 256];
__device__ __align__(16) unsigned short g_Ac_lo[NCL * 256];
__device__ __align__(16) unsigned short g_Al_hi[NLIT * 384];
__device__ __align__(16) unsigned short g_Al_lo[NLIT * 384];
// B packs: [quarter][kb][n=128][k=32] halves, hi and lo
__device__ __align__(16) unsigned short g_Bc_hi[4 * KBC * 128 * 32];
__device__ __align__(16) unsigned short g_Bc_lo[4 * KBC * 128 * 32];
__device__ __align__(16) unsigned short g_Bl_hi[4 * KBL * 128 * 32];
__device__ __align__(16) unsigned short g_Bl_lo[4 * KBL * 128 * 32];
__device__ float g_bp_c[NG];
__device__ float g_bp_l[NG];
__device__ float g_votes[NLIT];
// CSR: literal -> clause list (built once per replay)
__device__ int g_deg[NLIT];
__device__ int g_off[NLIT];
__device__ int g_pos[NLIT];
__device__ int g_csr[NEDGE];

// ---------------------------------------------------------------------------
// helpers
// ---------------------------------------------------------------------------
__device__ __forceinline__ uint32_t smem_u32(const void* p) {
    uint32_t a;
    asm("{ .reg .u64 t; cvta.to.shared.u64 t, %1; cvt.u32.u64 %0, t; }" : "=r"(a) : "l"(p));
    return a;
}

__device__ __forceinline__ void cvt2(float a, float b, uint32_t& hi, uint32_t& lo) {
    __nv_bfloat16 ah = __float2bfloat16(a), bh = __float2bfloat16(b);
    float ar = a - __bfloat162float(ah), br = b - __bfloat162float(bh);
    __nv_bfloat16 al = __float2bfloat16(ar), bl = __float2bfloat16(br);
    hi = (uint32_t)__bfloat16_as_ushort(ah) | ((uint32_t)__bfloat16_as_ushort(bh) << 16);
    lo = (uint32_t)__bfloat16_as_ushort(al) | ((uint32_t)__bfloat16_as_ushort(bl) << 16);
}

__device__ __forceinline__ float sigm(float x) { return 1.f / (1.f + expf(-x)); }

__device__ __forceinline__ void mma16816(float* d, const uint32_t* a,
                                         uint32_t b0, uint32_t b1) {
    asm volatile(
        "mma.sync.aligned.m16n8k16.row.col.f32.bf16.bf16.f32 "
        "{%0,%1,%2,%3},{%4,%5,%6,%7},{%8,%9},{%0,%1,%2,%3};"
        : "+f"(d[0]), "+f"(d[1]), "+f"(d[2]), "+f"(d[3])
        : "r"(a[0]), "r"(a[1]), "r"(a[2]), "r"(a[3]), "r"(b0), "r"(b1));
}

__device__ __forceinline__ void ldsm_x4(uint32_t* r, uint32_t addr) {
    asm volatile("ldmatrix.sync.aligned.m8n8.x4.shared.b16 {%0,%1,%2,%3}, [%4];"
        : "=r"(r[0]), "=r"(r[1]), "=r"(r[2]), "=r"(r[3]) : "r"(addr));
}

#define CP16(dst, src) \
    asm volatile("cp.async.cg.shared.global [%0], [%1], 16;" :: "r"(dst), "l"(src))
#define CP_COMMIT() asm volatile("cp.async.commit_group;" ::: "memory")

// ---------------------------------------------------------------------------
// Prep: pack weights bf16 hi/lo in [quarter][kb][n][k] order.
// Column packing within a 128-col quarter: c = 4*j_local + gate.
// ---------------------------------------------------------------------------
__global__ void k_prep(const float* __restrict__ Wih_lc, const float* __restrict__ Whh_lc,
                       const float* __restrict__ bih_lc, const float* __restrict__ bhh_lc,
                       const float* __restrict__ Wih_cl, const float* __restrict__ Whh_cl,
                       const float* __restrict__ bih_cl, const float* __restrict__ bhh_cl)
{
    int id = blockIdx.x * blockDim.x + threadIdx.x;
    const int CE = 4 * KBC * 128 * 32;
    const int LE = 4 * KBL * 128 * 32;
    if (id < CE) {
        int q  = id / (KBC * 4096);
        int r  = id % (KBC * 4096);
        int kb = r / 4096;
        int r2 = r % 4096;
        int n  = r2 >> 5, k = r2 & 31;
        int j = n >> 2, gate = n & 3;
        int ng = gate * 128 + q * 32 + j;
        int kg = kb * 32 + k;
        float v = (kg < 128) ? Wih_lc[ng * 128 + kg] : Whh_lc[ng * 128 + (kg - 128)];
        __nv_bfloat16 h = __float2bfloat16(v);
        __nv_bfloat16 l = __float2bfloat16(v - __bfloat162float(h));
        g_Bc_hi[id] = __bfloat16_as_ushort(h);
        g_Bc_lo[id] = __bfloat16_as_ushort(l);
    } else if (id < CE + LE) {
        int id2 = id - CE;
        int q  = id2 / (KBL * 4096);
        int r  = id2 % (KBL * 4096);
        int kb = r / 4096;
        int r2 = r % 4096;
        int n  = r2 >> 5, k = r2 & 31;
        int j = n >> 2, gate = n & 3;
        int ng = gate * 128 + q * 32 + j;
        int kg = kb * 32 + k;
        float v = (kg < 256) ? Wih_cl[ng * 256 + kg] : Whh_cl[ng * 128 + (kg - 256)];
        __nv_bfloat16 h = __float2bfloat16(v);
        __nv_bfloat16 l = __float2bfloat16(v - __bfloat162float(h));
        g_Bl_hi[id2] = __bfloat16_as_ushort(h);
        g_Bl_lo[id2] = __bfloat16_as_ushort(l);
    }
    if (id < NG) {
        int q = id >> 7, c = id & 127;
        int j = c >> 2, gate = c & 3;
        int ng = gate * 128 + q * 32 + j;
        g_bp_c[id] = bih_lc[ng] + bhh_lc[ng];
        g_bp_l[id] = bih_cl[ng] + bhh_cl[ng];
    }
}

__global__ void k_init(const float* __restrict__ x_unk,
                       const float* __restrict__ Cw, const float* __restrict__ Cb)
{
    int id = blockIdx.x * blockDim.x + threadIdx.x;
    if (id < NLIT * DD) { g_hl[0][id] = x_unk[id]; g_cl[id] = 0.f; }
    if (id < NCL * DD)  { g_hc[0][id] = Cw[id & 127] + Cb[id & 127]; g_cc[id] = 0.f; }
}

// ---------------------------------------------------------------------------
// CSR build: lit -> clause list
// ---------------------------------------------------------------------------
__global__ void k_csr_zero()
{
    int id = blockIdx.x * blockDim.x + threadIdx.x;
    if (id < NLIT) { g_deg[id] = 0; g_pos[id] = 0; }
}

__global__ void k_csr_count(const int* __restrict__ lit_idx)
{
    int e = blockIdx.x * blockDim.x + threadIdx.x;
    if (e < NEDGE) atomicAdd(&g_deg[lit_idx[e]], 1);
}

__global__ void k_csr_scan()
{
    __shared__ int sm[1024];
    __shared__ int carry;
    const int tid = threadIdx.x;
    if (tid == 0) carry = 0;
    __syncthreads();
    for (int chunk = 0; chunk < (NLIT + 1023) / 1024; chunk++) {
        int idx = chunk * 1024 + tid;
        int v = (idx < NLIT) ? g_deg[idx] : 0;
        sm[tid] = v;
        __syncthreads();
        for (int off = 1; off < 1024; off <<= 1) {
            int t = (tid >= off) ? sm[tid - off] : 0;
            __syncthreads();
            sm[tid] += t;
            __syncthreads();
        }
        int incl = sm[tid];
        int base = carry;
        if (idx < NLIT) g_off[idx] = base + incl - v;
        __syncthreads();
        if (tid == 1023) carry = base + incl;
        __syncthreads();
    }
}

__global__ void k_csr_fill(const int* __restrict__ lit_idx)
{
    int e = blockIdx.x * blockDim.x + threadIdx.x;
    if (e >= NEDGE) return;
    int lit = lit_idx[e];
    int p = atomicAdd(&g_pos[lit], 1);
    g_csr[g_off[lit] + p] = e / 3;   // clause id
}

// ---------------------------------------------------------------------------
// A conversion (fused gather): fp32 state -> bf16 hi/lo global tiles.
// MODE 0: A = [gather-sum3(h_l) | h_c], KTOT=256, rows=NCL
// MODE 1: A = [CSR-sum(h_c) | h_l[flip] | h_l], KTOT=384, rows=NLIT
// ---------------------------------------------------------------------------
template<int MODE>
__global__ void k_conv(const int* __restrict__ lit_idx,
                       const int* __restrict__ flip, int par)
{
    const int id = blockIdx.x * blockDim.x + threadIdx.x;
    float4 v;
    int row, c;
    if (MODE == 0) {
        if (id >= NCL * 64) return;
        row = id >> 6;
        c = (id & 63) << 2;
        if (c < 128) {
            const int i0 = lit_idx[3 * row], i1 = lit_idx[3 * row + 1], i2 = lit_idx[3 * row + 2];
            const float* hl = g_hl[par];
            float4 a = *(const float4*)(hl + (size_t)i0 * DD + c);
            float4 b = *(const float4*)(hl + (size_t)i1 * DD + c);
            float4 d = *(const float4*)(hl + (size_t)i2 * DD + c);
            v.x = a.x + b.x + d.x; v.y = a.y + b.y + d.y;
            v.z = a.z + b.z + d.z; v.w = a.w + b.w + d.w;
        } else {
            v = *(const float4*)(g_hc[par] + (size_t)row * DD + (c - 128));
        }
    } else {
        if (id >= NLIT * 96) return;
        row = id / 96;
        c = (id % 96) << 2;
        if (c < 128) {
            const float* hc = g_hc[par ^ 1];
            const int beg = g_off[row];
            const int end = beg + g_deg[row];
            v.x = 0.f; v.y = 0.f; v.z = 0.f; v.w = 0.f;
            for (int i = beg; i < end; i++) {
                const int cl = g_csr[i];
                float4 a = *(const float4*)(hc + (size_t)cl * DD + c);
                v.x += a.x; v.y += a.y; v.z += a.z; v.w += a.w;
            }
        }
        else if (c < 256) v = *(const float4*)(g_hl[par] + (size_t)flip[row] * DD + (c - 128));
        else              v = *(const float4*)(g_hl[par] + (size_t)row * DD + (c - 256));
    }
    uint2 hi, lo;
    cvt2(v.x, v.y, hi.x, lo.x);
    cvt2(v.z, v.w, hi.y, lo.y);
    const int KT = (MODE == 0) ? 256 : 384;
    unsigned short* Ah = (MODE == 0) ? g_Ac_hi : g_Al_hi;
    unsigned short* Al = (MODE == 0) ? g_Ac_lo : g_Al_lo;
    *(uint2*)(Ah + (size_t)row * KT + c) = hi;
    *(uint2*)(Al + (size_t)row * KT + c) = lo;
}

// ---------------------------------------------------------------------------
// Lean mma.sync GEMM + fused LSTM epilogue. A and B pre-converted bf16 hi/lo.
// CTA: 128 rows x 128 packed gate cols (quarter q = blockIdx.y), BK=32,
// 8 warps (4m x 2n), cp.async double buffer, bf16x3 split, fp32 accum.
// ldmatrix fragment loads; single barrier per k-block.
// ---------------------------------------------------------------------------
template<int MODE>
__global__ void __launch_bounds__(256, 2) k_gemm_mma(int par)
{
    constexpr int KB = (MODE == 0) ? KBC : KBL;
    constexpr int KT = KB * 32;
    extern __shared__ __align__(16) char smc[];
    const uint32_t s0 = smem_u32(smc);

    const int tid = threadIdx.x;
    const int wid = tid >> 5, lane = tid & 31;
    const int warp_m = wid & 3, warp_n = wid >> 2;
    const int t = lane & 3;
    const int mblk = blockIdx.x, q = blockIdx.y;

    float* __restrict__ hdst = (MODE == 0) ? g_hc[par ^ 1] : g_hl[par ^ 1];
    float* __restrict__ carr = (MODE == 0) ? g_cc : g_cl;
    const float* __restrict__ biasp = (MODE == 0) ? g_bp_c : g_bp_l;
    const unsigned short* __restrict__ Ahig = (MODE == 0) ? g_Ac_hi : g_Al_hi;
    const unsigned short* __restrict__ Alog = (MODE == 0) ? g_Ac_lo : g_Al_lo;
    const unsigned short* __restrict__ Bhig = (MODE == 0) ? g_Bc_hi : g_Bl_hi;
    const unsigned short* __restrict__ Blog = (MODE == 0) ? g_Bc_lo : g_Bl_lo;

    const int arow = tid >> 1;
    const int kh   = (tid & 1) * 16;

    const unsigned short* pah = Ahig + (size_t)(mblk * 128 + arow) * KT + kh;
    const unsigned short* pal = Alog + (size_t)(mblk * 128 + arow) * KT + kh;
    const unsigned short* pbh = Bhig + ((size_t)(q * KB) * 128 + arow) * 32 + kh;
    const unsigned short* pbl = Blog + ((size_t)(q * KB) * 128 + arow) * 32 + kh;
    const uint32_t sd = s0 + arow * PITCHB + kh * 2;

    // ldmatrix per-lane address components
    const int a_row_l = ((lane >> 3) & 1) * 8 + (lane & 7);   // row within 16-row frag
    const int a_koff  = (lane >> 4) * 16;                     // 0 or 16 bytes (k8-15)
    const int b_n_l   = ((lane >> 4) & 1) * 8 + (lane & 7);   // n within 16-n block
    const int b_koff  = ((lane >> 3) & 1) * 16;
    const uint32_t a_base = s0 + (warp_m * 32 + a_row_l) * PITCHB + a_koff;
    const uint32_t b_base = s0 + OFF_BHI + (warp_n * 64 + b_n_l) * PITCHB + b_koff;

    auto load_tiles = [&](int kbx, int buf) {
        const uint32_t d = sd + buf * BUF_BYTES;
        const unsigned short* a0 = pah + kbx * 32;
        const unsigned short* a1 = pal + kbx * 32;
        const unsigned short* b0 = pbh + (size_t)kbx * 4096;
        const unsigned short* b1 = pbl + (size_t)kbx * 4096;
        CP16(d, a0);                       CP16(d + 16, a0 + 8);
        CP16(d + OFF_ALO, a1);             CP16(d + OFF_ALO + 16, a1 + 8);
        CP16(d + OFF_BHI, b0);             CP16(d + OFF_BHI + 16, b0 + 8);
        CP16(d + OFF_BLO, b1);             CP16(d + OFF_BLO + 16, b1 + 8);
        CP_COMMIT();
    };

    float acc[2][8][4];
#pragma unroll
    for (int a = 0; a < 2; a++)
#pragma unroll
        for (int b = 0; b < 8; b++)
#pragma unroll
            for (int c = 0; c < 4; c++) acc[a][b][c] = 0.f;

    auto compute = [&](int buf) {
        const uint32_t ab = a_base + buf * BUF_BYTES;
        const uint32_t bbb = b_base + buf * BUF_BYTES;
#pragma unroll
        for (int ks = 0; ks < 2; ks++) {
            uint32_t ah[2][4], al[2][4];
#pragma unroll
            for (int mf = 0; mf < 2; mf++) {
                ldsm_x4(ah[mf], ab + mf * (16 * PITCHB) + ks * 32);
                ldsm_x4(al[mf], ab + OFF_ALO + mf * (16 * PITCHB) + ks * 32);
            }
#pragma unroll
            for (int nh = 0; nh < 2; nh++) {
                uint32_t bh[8], bl[8];
                ldsm_x4(bh,     bbb + (nh * 32) * PITCHB + ks * 32);
                ldsm_x4(bh + 4, bbb + (nh * 32 + 16) * PITCHB + ks * 32);
                ldsm_x4(bl,     bbb + 10240 + (nh * 32) * PITCHB + ks * 32);
                ldsm_x4(bl + 4, bbb + 10240 + (nh * 32 + 16) * PITCHB + ks * 32);
                // pass 1: Ahi * Bhi  (8 distinct accs)
#pragma unroll
                for (int f = 0; f < 4; f++)
#pragma unroll
                    for (int mf = 0; mf < 2; mf++)
                        mma16816(acc[mf][nh * 4 + f], ah[mf], bh[2 * f], bh[2 * f + 1]);
                // pass 2: Alo * Bhi
#pragma unroll
                for (int f = 0; f < 4; f++)
#pragma unroll
                    for (int mf = 0; mf < 2; mf++)
                        mma16816(acc[mf][nh * 4 + f], al[mf], bh[2 * f], bh[2 * f + 1]);
                // pass 3: Ahi * Blo
#pragma unroll
                for (int f = 0; f < 4; f++)
#pragma unroll
                    for (int mf = 0; mf < 2; mf++)
                        mma16816(acc[mf][nh * 4 + f], ah[mf], bl[2 * f], bl[2 * f + 1]);
            }
        }
    };

    load_tiles(0, 0);
#pragma unroll 1
    for (int kb = 0; kb < KB; kb++) {
        asm volatile("cp.async.wait_group 0;" ::: "memory");
        __syncthreads();
        if (kb + 1 < KB) load_tiles(kb + 1, (kb + 1) & 1);
        compute(kb & 1);
    }

    // ---- fused LSTM epilogue via lane-pair shfl ----
    const bool ev = (t & 1) == 0;
    const int g = lane >> 2;
#pragma unroll
    for (int mf = 0; mf < 2; mf++) {
#pragma unroll
        for (int nf = 0; nf < 8; nf++) {
            float c0 = acc[mf][nf][0], c1 = acc[mf][nf][1];
            float c2 = acc[mf][nf][2], c3 = acc[mf][nf][3];
            const int col0 = warp_n * 64 + nf * 8 + t * 2;
            const float2 bb2 = *(const float2*)(biasp + q * 128 + col0);
            c0 += bb2.x; c1 += bb2.y; c2 += bb2.x; c3 += bb2.y;
            float p0 = __shfl_xor_sync(0xffffffffu, c0, 1);
            float p1 = __shfl_xor_sync(0xffffffffu, c1, 1);
            float p2 = __shfl_xor_sync(0xffffffffu, c2, 1);
            float p3 = __shfl_xor_sync(0xffffffffu, c3, 1);
            float gi = ev ? c0 : p2;
            float gf = ev ? c1 : p3;
            float gg = ev ? p0 : c2;
            float go = ev ? p1 : c3;
            const int row = mblk * 128 + warp_m * 32 + mf * 16 + g + (ev ? 0 : 8);
            const int jloc = warp_n * 16 + nf * 2 + (t >> 1);
            const size_t off = (size_t)row * DD + q * 32 + jloc;
            float cold = carr[off];
            float cn = sigm(gf) * cold + sigm(gi) * tanhf(gg);
            float hn = sigm(go) * tanhf(cn);
            carr[off] = cn;
            hdst[off] = hn;
        }
    }
}

// ---------------------------------------------------------------------------
// readout
// ---------------------------------------------------------------------------
__global__ void k_votes(const float* __restrict__ ow, const float* __restrict__ ob)
{
    int gw   = (blockIdx.x * blockDim.x + threadIdx.x) >> 5;
    int lane = threadIdx.x & 31;
    if (gw >= NLIT) return;
    const float* h = g_hl[0] + (size_t)gw * DD;
    float s = 0.f;
    for (int j = lane; j < DD; j += 32) s += h[j] * ow[j];
#pragma unroll
    for (int o = 16; o > 0; o >>= 1) s += __shfl_down_sync(0xffffffffu, s, o);
    if (lane == 0) g_votes[gw] = s + ob[0];
}

__global__ void k_reduce(float* __restrict__ red)
{
    __shared__ float sm[256];
    int b = blockIdx.x;
    float s = 0.f;
    for (int i = threadIdx.x; i < GPL; i += 256) s += g_votes[b * GPL + i];
    sm[threadIdx.x] = s;
    __syncthreads();
    for (int o = 128; o > 0; o >>= 1) {
        if (threadIdx.x < o) sm[threadIdx.x] += sm[threadIdx.x + o];
        __syncthreads();
    }
    if (threadIdx.x == 0) red[b] = sm[0] / (float)GPL;
}

__global__ void k_copy_votes(float* __restrict__ dst)
{
    int id = blockIdx.x * blockDim.x + threadIdx.x;
    if (id < NLIT) dst[id] = g_votes[id];
}

__global__ void k_copy_hl(float* __restrict__ dst)
{
    int id = blockIdx.x * blockDim.x + threadIdx.x;
    if (id < NLIT * DD) dst[id] = g_hl[0][id];
}

// ---------------------------------------------------------------------------
// launch
// ---------------------------------------------------------------------------
extern "C" void kernel_launch(void* const* d_in, const int* in_sizes, int n_in,
                              void* d_out, int out_size)
{
    const float* x_unk   = (const float*)d_in[0];
    const float* C_w     = (const float*)d_in[1];
    const float* C_b     = (const float*)d_in[2];
    const float* Wih_lc  = (const float*)d_in[3];
    const float* Whh_lc  = (const float*)d_in[4];
    const float* bih_lc  = (const float*)d_in[5];
    const float* bhh_lc  = (const float*)d_in[6];
    const float* Wih_cl  = (const float*)d_in[7];
    const float* Whh_cl  = (const float*)d_in[8];
    const float* bih_cl  = (const float*)d_in[9];
    const float* bhh_cl  = (const float*)d_in[10];
    const float* out_w   = (const float*)d_in[11];
    const float* out_b   = (const float*)d_in[12];
    const int*   lit_idx = (const int*)d_in[13];
    const int*   clause_idx = (const int*)d_in[14];
    const int*   flip_perm  = (const int*)d_in[16];
    float* out = (float*)d_out;

    const int T = 256;

    cudaFuncSetAttribute(k_gemm_mma<0>, cudaFuncAttributeMaxDynamicSharedMemorySize, SMEMB);
    cudaFuncSetAttribute(k_gemm_mma<1>, cudaFuncAttributeMaxDynamicSharedMemorySize, SMEMB);

    const int prep_n = 4 * KBC * 128 * 32 + 4 * KBL * 128 * 32;
    k_prep<<<(prep_n + T - 1) / T, T>>>(Wih_lc, Whh_lc, bih_lc, bhh_lc,
                                        Wih_cl, Whh_cl, bih_cl, bhh_cl);
    k_init<<<(NCL * DD + T - 1) / T, T>>>(x_unk, C_w, C_b);

    // CSR build (once per replay)
    k_csr_zero<<<(NLIT + T - 1) / T, T>>>();
    k_csr_count<<<(NEDGE + T - 1) / T, T>>>(lit_idx);
    k_csr_scan<<<1, 1024>>>();
    k_csr_fill<<<(NEDGE + T - 1) / T, T>>>(lit_idx);

    dim3 gc(NCL / 128, 4);    // (500, 4)
    dim3 gl(NLIT / 128, 4);   // (250, 4)

    for (int it = 0; it < NITER; ++it) {
        int par = it & 1;
        k_conv<0><<<(NCL * 64 + T - 1) / T, T>>>(lit_idx, flip_perm, par);
        k_gemm_mma<0><<<gc, T, SMEMB>>>(par);
        k_conv<1><<<(NLIT * 96 + T - 1) / T, T>>>(lit_idx, flip_perm, par);
        k_gemm_mma<1><<<gl, T, SMEMB>>>(par);
    }

    k_votes<<<(NLIT * 32 + T - 1) / T, T>>>(out_w, out_b);
    if (out_size >= NB)
        k_reduce<<<NB, T>>>(out);
    if (out_size >= NB + NLIT)
        k_copy_votes<<<(NLIT + T - 1) / T, T>>>(out + NB);
    if (out_size >= NB + NLIT + NLIT * DD)
        k_copy_hl<<<(NLIT * DD + T - 1) / T, T>>>(out + NB + NLIT);
}